// round 8
// baseline (speedup 1.0000x reference)
#include <cuda_runtime.h>
#include <math.h>

#define BB 16
#define SS 1024
#define EE 256
#define HH 256
#define GG 1024
#define WT 256
#define MM (BB*SS)

// ---------------- scratch (__device__ globals; no alloc allowed) ----------------
__device__ float g_Zf[(size_t)MM*GG];
__device__ float g_Zb[(size_t)MM*GG];
__device__ float g_D [(size_t)MM*GG];
__device__ float g_hn[(size_t)MM*HH];
__device__ float g_hb[(size_t)MM*HH];
__device__ float g_Hd[(size_t)MM*HH];
__device__ float g_C [(size_t)MM*WT];
__device__ float g_U [(size_t)MM*WT];
__device__ float g_henc[2][2][BB][HH];   // [dir][parity][b][h]
__device__ float g_hdec[2][BB][HH];      // [parity][b][h]
__device__ unsigned int g_cnt_enc[2];
__device__ unsigned int g_cnt_dec[1];

__device__ __forceinline__ float sigf(float x){ return 1.0f/(1.0f+expf(-x)); }

// ---------------- per-replay state reset ----------------
__global__ void init_state()
{
    int i = blockIdx.x*blockDim.x + threadIdx.x;
    if (i < 2*2*BB*HH) (&g_henc[0][0][0][0])[i] = 0.0f;
    if (i < 2*BB*HH)   (&g_hdec[0][0][0])[i]   = 0.0f;
    if (i == 0) { g_cnt_enc[0]=0u; g_cnt_enc[1]=0u; g_cnt_dec[0]=0u; }
}

// ---------------- fp32 SGEMM: C (+)= A[M,K]@W[K,N] (+bias). 128x128 tile, BK=8 ----------------
__global__ __launch_bounds__(256) void sgemm128(
    const float* __restrict__ A, int lda,
    const float* __restrict__ W, int ldw,
    float* __restrict__ C, int ldc,
    int K, const float* __restrict__ bias, int accflag)
{
    __shared__ float As[8][132];
    __shared__ float Ws[8][128];
    const int tid = threadIdx.x;
    const int m0 = blockIdx.y << 7, n0 = blockIdx.x << 7;
    const int ar = tid >> 1, ac = tid & 1;
    const int wr = tid >> 5, wc = tid & 31;
    const int ty = tid >> 4, tx = tid & 15;
    float acc[8][8];
    #pragma unroll
    for (int i=0;i<8;i++){
        #pragma unroll
        for (int j=0;j<8;j++) acc[i][j]=0.0f;
    }
    const float* Ap = A + (size_t)(m0+ar)*lda + (ac<<2);
    const float* Wp = W + (size_t)wr*ldw + n0 + (wc<<2);
    for (int k0=0;k0<K;k0+=8) {
        float4 av = *(const float4*)(Ap + k0);
        float4 wv = *(const float4*)(Wp + (size_t)k0*ldw);
        As[(ac<<2)+0][ar]=av.x; As[(ac<<2)+1][ar]=av.y;
        As[(ac<<2)+2][ar]=av.z; As[(ac<<2)+3][ar]=av.w;
        *(float4*)&Ws[wr][wc<<2] = wv;
        __syncthreads();
        #pragma unroll
        for (int kk=0;kk<8;kk++) {
            float a[8], bv[8];
            *(float4*)&a[0]  = *(const float4*)&As[kk][ty<<3];
            *(float4*)&a[4]  = *(const float4*)&As[kk][(ty<<3)+4];
            *(float4*)&bv[0] = *(const float4*)&Ws[kk][tx<<3];
            *(float4*)&bv[4] = *(const float4*)&Ws[kk][(tx<<3)+4];
            #pragma unroll
            for (int i=0;i<8;i++){
                #pragma unroll
                for (int j=0;j<8;j++) acc[i][j] += a[i]*bv[j];
            }
        }
        __syncthreads();
    }
    #pragma unroll
    for (int i=0;i<8;i++) {
        float* crow = C + (size_t)(m0 + (ty<<3) + i)*ldc + n0 + (tx<<3);
        float4 v0 = make_float4(acc[i][0],acc[i][1],acc[i][2],acc[i][3]);
        float4 v1 = make_float4(acc[i][4],acc[i][5],acc[i][6],acc[i][7]);
        if (bias) {
            const float* bp = bias + n0 + (tx<<3);
            float4 b0=*(const float4*)bp, b1=*(const float4*)(bp+4);
            v0.x+=b0.x; v0.y+=b0.y; v0.z+=b0.z; v0.w+=b0.w;
            v1.x+=b1.x; v1.y+=b1.y; v1.z+=b1.z; v1.w+=b1.w;
        }
        if (accflag) {
            float4 c0=*(const float4*)crow, c1=*(const float4*)(crow+4);
            v0.x+=c0.x; v0.y+=c0.y; v0.z+=c0.z; v0.w+=c0.w;
            v1.x+=c1.x; v1.y+=c1.y; v1.z+=c1.z; v1.w+=c1.w;
        }
        *(float4*)crow = v0; *(float4*)(crow+4) = v1;
    }
}

// ---------------- encoder recurrence: grid (64,2); 4 hidden units/block ----------------
__global__ __launch_bounds__(256) void enc_rnn(const float* __restrict__ Whh_f,
                                               const float* __restrict__ Whh_b)
{
    const int NB = 64, J = 4, NC = 16;
    const int dir = blockIdx.y;
    const int j0  = blockIdx.x * J;
    const float* Whh = dir ? Whh_b : Whh_f;
    const float* Z   = dir ? g_Zb  : g_Zf;
    float* hout      = dir ? g_hb  : g_hn;
    __shared__ float Wsh[NC][260];
    __shared__ float hsh[BB][260];
    __shared__ float zsh[BB][NC];
    __shared__ float csh[BB][J];
    const int tid = threadIdx.x;
    for (int idx = tid; idx < NC*HH; idx += 256) {
        int c = idx & (NC-1), k = idx >> 4;
        int gc = ((c>>2)<<8) + j0 + (c&3);
        Wsh[c][k] = Whh[k*GG + gc];
    }
    if (tid < BB*J) csh[tid>>2][tid&3] = 0.0f;
    const int b = tid >> 4, c = tid & 15;
    const int gcol = ((c>>2)<<8) + j0 + (c&3);
    __syncthreads();
    for (int t = 0; t < SS; ++t) {
        if (tid == 0) {
            unsigned target = (unsigned)(NB * t);
            while (*(volatile unsigned int*)&g_cnt_enc[dir] < target) __nanosleep(32);
        }
        __syncthreads();
        const float4* hg = (const float4*)&g_henc[dir][t & 1][0][0];
        for (int idx = tid; idx < BB*HH/4; idx += 256) {
            float4 v = __ldcg(hg + idx);
            *(float4*)&hsh[idx>>6][(idx&63)<<2] = v;
        }
        __syncthreads();
        const int tt = dir ? (SS-1-t) : t;
        float acc = Z[(((size_t)b<<10) + tt)*GG + gcol];
        #pragma unroll 16
        for (int k = 0; k < HH; k += 4) {
            float4 hv = *(const float4*)&hsh[b][k];
            float4 wv = *(const float4*)&Wsh[c][k];
            acc += hv.x*wv.x; acc += hv.y*wv.y; acc += hv.z*wv.z; acc += hv.w*wv.w;
        }
        zsh[b][c] = acc;
        __syncthreads();
        if (c < J) {
            const int jj = c;
            float zi = zsh[b][jj], zf = zsh[b][J+jj], zg = zsh[b][2*J+jj], zo = zsh[b][3*J+jj];
            float cc = sigf(zf)*csh[b][jj] + sigf(zi)*tanhf(zg);
            float hh = sigf(zo)*tanhf(cc);
            csh[b][jj] = cc;
            const int j = j0 + jj;
            g_henc[dir][(t+1)&1][b][j] = hh;
            hout[(((size_t)b<<10) + tt)*HH + j] = hh;
        }
        __threadfence();
        __syncthreads();
        if (tid == 0) atomicAdd(&g_cnt_enc[dir], 1u);
    }
}

// ---------------- decoder recurrence: 64 blocks; 4 hidden units/block ----------------
// z_t = dec_b + (t>0 ? D[b][t-1] : 0) + h@Whh ; h0 = 0, c0 = hn[b][S-1]. Stores Hd[t]=h2.
__global__ __launch_bounds__(256) void dec_rnn(const float* __restrict__ Whh,
                                               const float* __restrict__ bias)
{
    const int NB = 64, J = 4, NC = 16;
    const int j0 = blockIdx.x * J;
    __shared__ float Wsh[NC][260];
    __shared__ float hsh[BB][260];
    __shared__ float zsh[BB][NC];
    __shared__ float csh[BB][J];
    const int tid = threadIdx.x;
    for (int idx = tid; idx < NC*HH; idx += 256) {
        int c = idx & 15, k = idx >> 4;
        int gc = ((c>>2)<<8) + j0 + (c&3);
        Wsh[c][k] = Whh[k*GG + gc];
    }
    if (tid < BB*J) {
        int bb = tid>>2, jj = tid&3;
        csh[bb][jj] = g_hn[(((size_t)bb<<10) + (SS-1))*HH + j0 + jj];
    }
    const int b = tid >> 4, c = tid & 15;
    const int gcol = ((c>>2)<<8) + j0 + (c&3);
    const float bz = bias[gcol];
    __syncthreads();
    for (int t = 0; t < SS; ++t) {
        if (tid == 0) {
            unsigned target = (unsigned)(NB * t);
            while (*(volatile unsigned int*)&g_cnt_dec[0] < target) __nanosleep(32);
        }
        __syncthreads();
        const float4* hg = (const float4*)&g_hdec[t & 1][0][0];
        for (int idx = tid; idx < BB*HH/4; idx += 256) {
            float4 v = __ldcg(hg + idx);
            *(float4*)&hsh[idx>>6][(idx&63)<<2] = v;
        }
        __syncthreads();
        float acc = bz + (t > 0 ? g_D[(((size_t)b<<10) + t - 1)*GG + gcol] : 0.0f);
        #pragma unroll 16
        for (int k = 0; k < HH; k += 4) {
            float4 hv = *(const float4*)&hsh[b][k];
            float4 wv = *(const float4*)&Wsh[c][k];
            acc += hv.x*wv.x; acc += hv.y*wv.y; acc += hv.z*wv.z; acc += hv.w*wv.w;
        }
        zsh[b][c] = acc;
        __syncthreads();
        if (c < J) {
            const int jj = c;
            float zi = zsh[b][jj], zf = zsh[b][J+jj], zg = zsh[b][2*J+jj], zo = zsh[b][3*J+jj];
            float cc = sigf(zf)*csh[b][jj] + sigf(zi)*tanhf(zg);
            float hh = sigf(zo)*tanhf(cc);
            csh[b][jj] = cc;
            const int j = j0 + jj;
            g_hdec[(t+1)&1][b][j] = hh;
            g_Hd[(((size_t)b<<10) + t)*HH + j] = hh;
        }
        __threadfence();
        __syncthreads();
        if (tid == 0) atomicAdd(&g_cnt_dec[0], 1u);
    }
}

// ---------------- bond chain: one block per batch; lazy masked argmax ----------------
__global__ __launch_bounds__(256) void chain_kernel(const float* __restrict__ vt1,
                                                    float* __restrict__ out)
{
    const int b = blockIdx.x, tid = threadIdx.x;
    __shared__ float v[WT], u[WT];
    __shared__ float smax[256];
    __shared__ int   sidx[256];
    for (int i = tid; i < WT; i += 256) v[i] = vt1[i];
    for (int s = tid; s < SS; s += 256) out[s*BB + b] = 0.0f;   // d_out poisoned
    __syncthreads();
    int bond = 0;
    for (int iter = 0; iter < SS; ++iter) {
        const int t = bond;
        for (int i = tid; i < WT; i += 256) u[i] = g_U[(((size_t)b<<10) + t)*WT + i];
        __syncthreads();
        float best = -INFINITY; int bidx = SS;
        for (int j = t + tid; j < SS; j += 256) {
            const float* crow = &g_C[(((size_t)b<<10) + j)*WT];
            float acc = 0.0f;
            #pragma unroll 8
            for (int k = 0; k < WT; k += 4) {
                float4 cv = *(const float4*)&crow[k];
                float4 uv = *(const float4*)&u[k];
                float4 vv = *(const float4*)&v[k];
                acc += tanhf(cv.x+uv.x)*vv.x;
                acc += tanhf(cv.y+uv.y)*vv.y;
                acc += tanhf(cv.z+uv.z)*vv.z;
                acc += tanhf(cv.w+uv.w)*vv.w;
            }
            if (acc > best) { best = acc; bidx = j; }
        }
        smax[tid] = best; sidx[tid] = bidx;
        __syncthreads();
        for (int off = 128; off; off >>= 1) {
            if (tid < off) {
                float ov = smax[tid+off]; int oi = sidx[tid+off];
                if (ov > smax[tid] || (ov == smax[tid] && oi < sidx[tid])) { smax[tid]=ov; sidx[tid]=oi; }
            }
            __syncthreads();
        }
        const int r = sidx[0];
        if (tid == 0) out[r*BB + b] = 1.0f;
        __syncthreads();
        if (r == t) break;
        bond = r;
    }
}

extern "C" void kernel_launch(void* const* d_in, const int* in_sizes, int n_in,
                              void* d_out, int out_size)
{
    const float* x    = (const float*)d_in[0];
    const float* eWf  = (const float*)d_in[1];
    const float* eUf  = (const float*)d_in[2];
    const float* ebf  = (const float*)d_in[3];
    const float* eWb  = (const float*)d_in[4];
    const float* eUb  = (const float*)d_in[5];
    const float* ebb  = (const float*)d_in[6];
    const float* dW   = (const float*)d_in[7];   // [512,1024]
    const float* dU   = (const float*)d_in[8];
    const float* db   = (const float*)d_in[9];
    const float* W1   = (const float*)d_in[10];  // [512,256]
    const float* W2   = (const float*)d_in[11];
    const float* W3   = (const float*)d_in[12];
    const float* W4   = (const float*)d_in[13];
    const float* vt1  = (const float*)d_in[14];
    float* out = (float*)d_out;

    float *Zf, *Zb, *D, *hn, *hb, *Hd, *C, *U;
    cudaGetSymbolAddress((void**)&Zf, g_Zf);
    cudaGetSymbolAddress((void**)&Zb, g_Zb);
    cudaGetSymbolAddress((void**)&D,  g_D);
    cudaGetSymbolAddress((void**)&hn, g_hn);
    cudaGetSymbolAddress((void**)&hb, g_hb);
    cudaGetSymbolAddress((void**)&Hd, g_Hd);
    cudaGetSymbolAddress((void**)&C,  g_C);
    cudaGetSymbolAddress((void**)&U,  g_U);

    init_state<<<64, 256>>>();

    dim3 gW(GG/128, MM/128);   // N=1024
    dim3 gN(WT/128, MM/128);   // N=256
    sgemm128<<<gW,256>>>(x, EE, eWf, GG, Zf, GG, EE, ebf, 0);
    sgemm128<<<gW,256>>>(x, EE, eWb, GG, Zb, GG, EE, ebb, 0);
    enc_rnn<<<dim3(64,2),256>>>(eUf, eUb);
    sgemm128<<<gW,256>>>(x,  EE, dW,             GG, D, GG, EE, nullptr, 0);
    sgemm128<<<gW,256>>>(hn, HH, dW + 256*GG,    GG, D, GG, HH, nullptr, 1);
    dec_rnn<<<64,256>>>(dU, db);
    sgemm128<<<gN,256>>>(hn, HH, W1,            WT, C, WT, HH, nullptr, 0);
    sgemm128<<<gN,256>>>(hb, HH, W1 + 256*WT,   WT, C, WT, HH, nullptr, 1);
    sgemm128<<<gN,256>>>(x,  EE, W2,            WT, C, WT, EE, nullptr, 1);
    sgemm128<<<gN,256>>>(x,  EE, W3,            WT, U, WT, EE, nullptr, 0);
    sgemm128<<<gN,256>>>(Hd, HH, W4,            WT, U, WT, HH, nullptr, 1);
    chain_kernel<<<BB,256>>>(vt1, out);
}

// round 9
// speedup vs baseline: 1.0023x; 1.0023x over previous
#include <cuda_runtime.h>
#include <math.h>

#define BB 16
#define SS 1024
#define EE 256
#define HH 256
#define GG 1024
#define WT 256
#define MM (BB*SS)

// ---------------- scratch (__device__ globals; no alloc allowed) ----------------
__device__ float g_Zf[(size_t)MM*GG];
__device__ float g_Zb[(size_t)MM*GG];
__device__ float g_D [(size_t)MM*GG];
__device__ float g_hn[(size_t)MM*HH];
__device__ float g_hb[(size_t)MM*HH];
__device__ float g_Hd[(size_t)MM*HH];
__device__ float g_C [(size_t)MM*WT];
__device__ float g_U [(size_t)MM*WT];
__device__ float g_henc[2][2][BB][HH];   // [dir][parity][b][h]
__device__ float g_hdec[2][BB][HH];      // [parity][b][h]
__device__ unsigned int g_cnt_enc[2];
__device__ unsigned int g_cnt_dec[1];

__device__ __forceinline__ float sigf(float x){ return 1.0f/(1.0f+expf(-x)); }

// ---------------- per-replay state reset ----------------
__global__ void init_state()
{
    int i = blockIdx.x*blockDim.x + threadIdx.x;
    if (i < 2*2*BB*HH) (&g_henc[0][0][0][0])[i] = 0.0f;
    if (i < 2*BB*HH)   (&g_hdec[0][0][0])[i]   = 0.0f;
    if (i == 0) { g_cnt_enc[0]=0u; g_cnt_enc[1]=0u; g_cnt_dec[0]=0u; }
}

// ---------------- fp32 SGEMM, double-buffered, packed f32x2 FMA ----------------
// C (+)= A[M,K] @ W[K,N] (+bias). 128x128 tile, BK=8, 256 threads, 8x8/thread.
__global__ __launch_bounds__(256, 2) void sgemm_db(
    const float* __restrict__ A, int lda,
    const float* __restrict__ W, int ldw,
    float* __restrict__ C, int ldc,
    int K, const float* __restrict__ bias, int accflag)
{
    __shared__ float As[2][8][132];
    __shared__ float Ws[2][8][132];
    const int tid = threadIdx.x;
    const int m0 = blockIdx.y << 7, n0 = blockIdx.x << 7;
    const int ar = tid >> 1, ac = tid & 1;        // A tile loader: row, k-quad
    const int wr = tid >> 5, wc = tid & 31;       // W tile loader: k-row, col-quad
    const int ty = tid >> 4, tx = tid & 15;       // compute: 8 rows x 8 cols

    unsigned long long acc2[8][4];
    #pragma unroll
    for (int i=0;i<8;i++){
        #pragma unroll
        for (int j=0;j<4;j++) acc2[i][j] = 0ull;
    }

    const float* Ap = A + (size_t)(m0+ar)*lda + (ac<<2);
    const float* Wp = W + (size_t)wr*ldw + n0 + (wc<<2);

    // prologue: stage 0
    {
        float4 av = *(const float4*)(Ap);
        float4 wv = *(const float4*)(Wp);
        As[0][(ac<<2)+0][ar]=av.x; As[0][(ac<<2)+1][ar]=av.y;
        As[0][(ac<<2)+2][ar]=av.z; As[0][(ac<<2)+3][ar]=av.w;
        *(float4*)&Ws[0][wr][wc<<2] = wv;
    }
    __syncthreads();

    const int NIT = K >> 3;
    int buf = 0;
    for (int it = 1; it <= NIT; ++it) {
        float4 av, wv;
        if (it < NIT) {
            av = *(const float4*)(Ap + (it<<3));
            wv = *(const float4*)(Wp + (size_t)(it<<3)*ldw);
        }
        // compute on current buffer
        #pragma unroll
        for (int kk=0;kk<8;kk++) {
            float4 af0 = *(const float4*)&As[buf][kk][ty<<3];
            float4 af1 = *(const float4*)&As[buf][kk][(ty<<3)+4];
            ulonglong2 q0 = *(const ulonglong2*)&Ws[buf][kk][tx<<3];
            ulonglong2 q1 = *(const ulonglong2*)&Ws[buf][kk][(tx<<3)+4];
            unsigned long long a2[8];
            asm("mov.b64 %0,{%1,%1};" : "=l"(a2[0]) : "f"(af0.x));
            asm("mov.b64 %0,{%1,%1};" : "=l"(a2[1]) : "f"(af0.y));
            asm("mov.b64 %0,{%1,%1};" : "=l"(a2[2]) : "f"(af0.z));
            asm("mov.b64 %0,{%1,%1};" : "=l"(a2[3]) : "f"(af0.w));
            asm("mov.b64 %0,{%1,%1};" : "=l"(a2[4]) : "f"(af1.x));
            asm("mov.b64 %0,{%1,%1};" : "=l"(a2[5]) : "f"(af1.y));
            asm("mov.b64 %0,{%1,%1};" : "=l"(a2[6]) : "f"(af1.z));
            asm("mov.b64 %0,{%1,%1};" : "=l"(a2[7]) : "f"(af1.w));
            #pragma unroll
            for (int i=0;i<8;i++) {
                asm("fma.rn.f32x2 %0,%1,%2,%0;" : "+l"(acc2[i][0]) : "l"(a2[i]), "l"(q0.x));
                asm("fma.rn.f32x2 %0,%1,%2,%0;" : "+l"(acc2[i][1]) : "l"(a2[i]), "l"(q0.y));
                asm("fma.rn.f32x2 %0,%1,%2,%0;" : "+l"(acc2[i][2]) : "l"(a2[i]), "l"(q1.x));
                asm("fma.rn.f32x2 %0,%1,%2,%0;" : "+l"(acc2[i][3]) : "l"(a2[i]), "l"(q1.y));
            }
        }
        if (it < NIT) {
            int nb = buf ^ 1;
            As[nb][(ac<<2)+0][ar]=av.x; As[nb][(ac<<2)+1][ar]=av.y;
            As[nb][(ac<<2)+2][ar]=av.z; As[nb][(ac<<2)+3][ar]=av.w;
            *(float4*)&Ws[nb][wr][wc<<2] = wv;
            __syncthreads();
            buf = nb;
        }
    }

    // epilogue
    #pragma unroll
    for (int i=0;i<8;i++) {
        float2 p0 = *reinterpret_cast<float2*>(&acc2[i][0]);
        float2 p1 = *reinterpret_cast<float2*>(&acc2[i][1]);
        float2 p2 = *reinterpret_cast<float2*>(&acc2[i][2]);
        float2 p3 = *reinterpret_cast<float2*>(&acc2[i][3]);
        float4 v0 = make_float4(p0.x, p0.y, p1.x, p1.y);
        float4 v1 = make_float4(p2.x, p2.y, p3.x, p3.y);
        float* crow = C + (size_t)(m0 + (ty<<3) + i)*ldc + n0 + (tx<<3);
        if (bias) {
            const float* bp = bias + n0 + (tx<<3);
            float4 b0=*(const float4*)bp, b1=*(const float4*)(bp+4);
            v0.x+=b0.x; v0.y+=b0.y; v0.z+=b0.z; v0.w+=b0.w;
            v1.x+=b1.x; v1.y+=b1.y; v1.z+=b1.z; v1.w+=b1.w;
        }
        if (accflag) {
            float4 c0=*(const float4*)crow, c1=*(const float4*)(crow+4);
            v0.x+=c0.x; v0.y+=c0.y; v0.z+=c0.z; v0.w+=c0.w;
            v1.x+=c1.x; v1.y+=c1.y; v1.z+=c1.z; v1.w+=c1.w;
        }
        *(float4*)crow = v0; *(float4*)(crow+4) = v1;
    }
}

// ---------------- encoder recurrence: grid (64,2); 4 hidden units/block ----------------
__global__ __launch_bounds__(256) void enc_rnn(const float* __restrict__ Whh_f,
                                               const float* __restrict__ Whh_b)
{
    const int NB = 64, J = 4, NC = 16;
    const int dir = blockIdx.y;
    const int j0  = blockIdx.x * J;
    const float* Whh = dir ? Whh_b : Whh_f;
    const float* Z   = dir ? g_Zb  : g_Zf;
    float* hout      = dir ? g_hb  : g_hn;
    __shared__ float Wsh[NC][260];
    __shared__ float hsh[BB][260];
    __shared__ float zsh[BB][NC];
    __shared__ float csh[BB][J];
    const int tid = threadIdx.x;
    for (int idx = tid; idx < NC*HH; idx += 256) {
        int c = idx & (NC-1), k = idx >> 4;
        int gc = ((c>>2)<<8) + j0 + (c&3);
        Wsh[c][k] = Whh[k*GG + gc];
    }
    if (tid < BB*J) csh[tid>>2][tid&3] = 0.0f;
    const int b = tid >> 4, c = tid & 15;
    const int gcol = ((c>>2)<<8) + j0 + (c&3);
    __syncthreads();
    for (int t = 0; t < SS; ++t) {
        if (tid == 0) {
            unsigned target = (unsigned)(NB * t);
            while (*(volatile unsigned int*)&g_cnt_enc[dir] < target) __nanosleep(32);
        }
        __syncthreads();
        const float4* hg = (const float4*)&g_henc[dir][t & 1][0][0];
        for (int idx = tid; idx < BB*HH/4; idx += 256) {
            float4 v = __ldcg(hg + idx);
            *(float4*)&hsh[idx>>6][(idx&63)<<2] = v;
        }
        __syncthreads();
        const int tt = dir ? (SS-1-t) : t;
        float acc = Z[(((size_t)b<<10) + tt)*GG + gcol];
        #pragma unroll 16
        for (int k = 0; k < HH; k += 4) {
            float4 hv = *(const float4*)&hsh[b][k];
            float4 wv = *(const float4*)&Wsh[c][k];
            acc += hv.x*wv.x; acc += hv.y*wv.y; acc += hv.z*wv.z; acc += hv.w*wv.w;
        }
        zsh[b][c] = acc;
        __syncthreads();
        if (c < J) {
            const int jj = c;
            float zi = zsh[b][jj], zf = zsh[b][J+jj], zg = zsh[b][2*J+jj], zo = zsh[b][3*J+jj];
            float cc = sigf(zf)*csh[b][jj] + sigf(zi)*tanhf(zg);
            float hh = sigf(zo)*tanhf(cc);
            csh[b][jj] = cc;
            const int j = j0 + jj;
            g_henc[dir][(t+1)&1][b][j] = hh;
            hout[(((size_t)b<<10) + tt)*HH + j] = hh;
        }
        __threadfence();
        __syncthreads();
        if (tid == 0) atomicAdd(&g_cnt_enc[dir], 1u);
    }
}

// ---------------- decoder recurrence: 64 blocks; 4 hidden units/block ----------------
__global__ __launch_bounds__(256) void dec_rnn(const float* __restrict__ Whh,
                                               const float* __restrict__ bias)
{
    const int NB = 64, J = 4, NC = 16;
    const int j0 = blockIdx.x * J;
    __shared__ float Wsh[NC][260];
    __shared__ float hsh[BB][260];
    __shared__ float zsh[BB][NC];
    __shared__ float csh[BB][J];
    const int tid = threadIdx.x;
    for (int idx = tid; idx < NC*HH; idx += 256) {
        int c = idx & 15, k = idx >> 4;
        int gc = ((c>>2)<<8) + j0 + (c&3);
        Wsh[c][k] = Whh[k*GG + gc];
    }
    if (tid < BB*J) {
        int bb = tid>>2, jj = tid&3;
        csh[bb][jj] = g_hn[(((size_t)bb<<10) + (SS-1))*HH + j0 + jj];
    }
    const int b = tid >> 4, c = tid & 15;
    const int gcol = ((c>>2)<<8) + j0 + (c&3);
    const float bz = bias[gcol];
    __syncthreads();
    for (int t = 0; t < SS; ++t) {
        if (tid == 0) {
            unsigned target = (unsigned)(NB * t);
            while (*(volatile unsigned int*)&g_cnt_dec[0] < target) __nanosleep(32);
        }
        __syncthreads();
        const float4* hg = (const float4*)&g_hdec[t & 1][0][0];
        for (int idx = tid; idx < BB*HH/4; idx += 256) {
            float4 v = __ldcg(hg + idx);
            *(float4*)&hsh[idx>>6][(idx&63)<<2] = v;
        }
        __syncthreads();
        float acc = bz + (t > 0 ? g_D[(((size_t)b<<10) + t - 1)*GG + gcol] : 0.0f);
        #pragma unroll 16
        for (int k = 0; k < HH; k += 4) {
            float4 hv = *(const float4*)&hsh[b][k];
            float4 wv = *(const float4*)&Wsh[c][k];
            acc += hv.x*wv.x; acc += hv.y*wv.y; acc += hv.z*wv.z; acc += hv.w*wv.w;
        }
        zsh[b][c] = acc;
        __syncthreads();
        if (c < J) {
            const int jj = c;
            float zi = zsh[b][jj], zf = zsh[b][J+jj], zg = zsh[b][2*J+jj], zo = zsh[b][3*J+jj];
            float cc = sigf(zf)*csh[b][jj] + sigf(zi)*tanhf(zg);
            float hh = sigf(zo)*tanhf(cc);
            csh[b][jj] = cc;
            const int j = j0 + jj;
            g_hdec[(t+1)&1][b][j] = hh;
            g_Hd[(((size_t)b<<10) + t)*HH + j] = hh;
        }
        __threadfence();
        __syncthreads();
        if (tid == 0) atomicAdd(&g_cnt_dec[0], 1u);
    }
}

// ---------------- bond chain: one block per batch; lazy masked argmax ----------------
__global__ __launch_bounds__(256) void chain_kernel(const float* __restrict__ vt1,
                                                    float* __restrict__ out)
{
    const int b = blockIdx.x, tid = threadIdx.x;
    __shared__ float v[WT], u[WT];
    __shared__ float smax[256];
    __shared__ int   sidx[256];
    for (int i = tid; i < WT; i += 256) v[i] = vt1[i];
    for (int s = tid; s < SS; s += 256) out[s*BB + b] = 0.0f;   // d_out poisoned
    __syncthreads();
    int bond = 0;
    for (int iter = 0; iter < SS; ++iter) {
        const int t = bond;
        for (int i = tid; i < WT; i += 256) u[i] = g_U[(((size_t)b<<10) + t)*WT + i];
        __syncthreads();
        float best = -INFINITY; int bidx = SS;
        for (int j = t + tid; j < SS; j += 256) {
            const float* crow = &g_C[(((size_t)b<<10) + j)*WT];
            float acc = 0.0f;
            #pragma unroll 8
            for (int k = 0; k < WT; k += 4) {
                float4 cv = *(const float4*)&crow[k];
                float4 uv = *(const float4*)&u[k];
                float4 vv = *(const float4*)&v[k];
                acc += tanhf(cv.x+uv.x)*vv.x;
                acc += tanhf(cv.y+uv.y)*vv.y;
                acc += tanhf(cv.z+uv.z)*vv.z;
                acc += tanhf(cv.w+uv.w)*vv.w;
            }
            if (acc > best) { best = acc; bidx = j; }
        }
        smax[tid] = best; sidx[tid] = bidx;
        __syncthreads();
        for (int off = 128; off; off >>= 1) {
            if (tid < off) {
                float ov = smax[tid+off]; int oi = sidx[tid+off];
                if (ov > smax[tid] || (ov == smax[tid] && oi < sidx[tid])) { smax[tid]=ov; sidx[tid]=oi; }
            }
            __syncthreads();
        }
        const int r = sidx[0];
        if (tid == 0) out[r*BB + b] = 1.0f;
        __syncthreads();
        if (r == t) break;
        bond = r;
    }
}

extern "C" void kernel_launch(void* const* d_in, const int* in_sizes, int n_in,
                              void* d_out, int out_size)
{
    const float* x    = (const float*)d_in[0];
    const float* eWf  = (const float*)d_in[1];
    const float* eUf  = (const float*)d_in[2];
    const float* ebf  = (const float*)d_in[3];
    const float* eWb  = (const float*)d_in[4];
    const float* eUb  = (const float*)d_in[5];
    const float* ebb  = (const float*)d_in[6];
    const float* dW   = (const float*)d_in[7];   // [512,1024]
    const float* dU   = (const float*)d_in[8];
    const float* db   = (const float*)d_in[9];
    const float* W1   = (const float*)d_in[10];  // [512,256]
    const float* W2   = (const float*)d_in[11];
    const float* W3   = (const float*)d_in[12];
    const float* W4   = (const float*)d_in[13];
    const float* vt1  = (const float*)d_in[14];
    float* out = (float*)d_out;

    float *Zf, *Zb, *D, *hn, *hb, *Hd, *C, *U;
    cudaGetSymbolAddress((void**)&Zf, g_Zf);
    cudaGetSymbolAddress((void**)&Zb, g_Zb);
    cudaGetSymbolAddress((void**)&D,  g_D);
    cudaGetSymbolAddress((void**)&hn, g_hn);
    cudaGetSymbolAddress((void**)&hb, g_hb);
    cudaGetSymbolAddress((void**)&Hd, g_Hd);
    cudaGetSymbolAddress((void**)&C,  g_C);
    cudaGetSymbolAddress((void**)&U,  g_U);

    init_state<<<64, 256>>>();

    dim3 gW(GG/128, MM/128);   // N=1024
    dim3 gN(WT/128, MM/128);   // N=256
    sgemm_db<<<gW,256>>>(x, EE, eWf, GG, Zf, GG, EE, ebf, 0);
    sgemm_db<<<gW,256>>>(x, EE, eWb, GG, Zb, GG, EE, ebb, 0);
    sgemm_db<<<gW,256>>>(x, EE, dW,              GG, D, GG, EE, nullptr, 0);
    enc_rnn<<<dim3(64,2),256>>>(eUf, eUb);
    sgemm_db<<<gW,256>>>(hn, HH, dW + 256*GG,    GG, D, GG, HH, nullptr, 1);
    sgemm_db<<<gN,256>>>(hn, HH, W1,            WT, C, WT, HH, nullptr, 0);
    sgemm_db<<<gN,256>>>(hb, HH, W1 + 256*WT,   WT, C, WT, HH, nullptr, 1);
    sgemm_db<<<gN,256>>>(x,  EE, W2,            WT, C, WT, EE, nullptr, 1);
    sgemm_db<<<gN,256>>>(x,  EE, W3,            WT, U, WT, EE, nullptr, 0);
    dec_rnn<<<64,256>>>(dU, db);
    sgemm_db<<<gN,256>>>(Hd, HH, W4,            WT, U, WT, HH, nullptr, 1);
    chain_kernel<<<BB,256>>>(vt1, out);
}

// round 10
// speedup vs baseline: 1.2675x; 1.2646x over previous
#include <cuda_runtime.h>
#include <math.h>

#define BB 16
#define SS 1024
#define EE 256
#define HH 256
#define GG 1024
#define WT 256
#define MM (BB*SS)
#define CL 8

// ---------------- scratch (__device__ globals; no alloc allowed) ----------------
__device__ float g_Zf[(size_t)MM*GG];
__device__ float g_Zb[(size_t)MM*GG];
__device__ float g_D [(size_t)MM*GG];
__device__ float g_hn[(size_t)MM*HH];
__device__ float g_hb[(size_t)MM*HH];
__device__ float g_Hd[(size_t)MM*HH];
__device__ float g_C [(size_t)MM*WT];
__device__ float g_U [(size_t)MM*WT];

__device__ __forceinline__ float sigf(float x){ return 1.0f/(1.0f+expf(-x)); }
__device__ __forceinline__ float hadd2(unsigned long long v){
    float2 f = *reinterpret_cast<float2*>(&v); return f.x + f.y;
}
#define FMA2(acc,a,b) asm("fma.rn.f32x2 %0,%1,%2,%0;" : "+l"(acc) : "l"(a), "l"(b))

// Dynamic smem layout (floats):
//   Wsh: 128 cols x 260           -> [0, 33280)
//   hsh: 2 bufs x 4 b x 260       -> [33280, 35360)
//   zsh: 4 b x 4 gates x 32       -> [35360, 35872)
#define W_OFF 0
#define H_OFF 33280
#define Z_OFF 35360
#define SMEM_FLOATS 35872
#define SMEM_BYTES (SMEM_FLOATS*4)

// ---------------- fp32 SGEMM, double-buffered, packed f32x2 FMA ----------------
__global__ __launch_bounds__(256, 2) void sgemm_db(
    const float* __restrict__ A, int lda,
    const float* __restrict__ W, int ldw,
    float* __restrict__ C, int ldc,
    int K, const float* __restrict__ bias, int accflag)
{
    __shared__ float As[2][8][132];
    __shared__ float Ws[2][8][132];
    const int tid = threadIdx.x;
    const int m0 = blockIdx.y << 7, n0 = blockIdx.x << 7;
    const int ar = tid >> 1, ac = tid & 1;
    const int wr = tid >> 5, wc = tid & 31;
    const int ty = tid >> 4, tx = tid & 15;

    unsigned long long acc2[8][4];
    #pragma unroll
    for (int i=0;i<8;i++){
        #pragma unroll
        for (int j=0;j<4;j++) acc2[i][j] = 0ull;
    }
    const float* Ap = A + (size_t)(m0+ar)*lda + (ac<<2);
    const float* Wp = W + (size_t)wr*ldw + n0 + (wc<<2);
    {
        float4 av = *(const float4*)(Ap);
        float4 wv = *(const float4*)(Wp);
        As[0][(ac<<2)+0][ar]=av.x; As[0][(ac<<2)+1][ar]=av.y;
        As[0][(ac<<2)+2][ar]=av.z; As[0][(ac<<2)+3][ar]=av.w;
        *(float4*)&Ws[0][wr][wc<<2] = wv;
    }
    __syncthreads();
    const int NIT = K >> 3;
    int buf = 0;
    for (int it = 1; it <= NIT; ++it) {
        float4 av, wv;
        if (it < NIT) {
            av = *(const float4*)(Ap + (it<<3));
            wv = *(const float4*)(Wp + (size_t)(it<<3)*ldw);
        }
        #pragma unroll
        for (int kk=0;kk<8;kk++) {
            float4 af0 = *(const float4*)&As[buf][kk][ty<<3];
            float4 af1 = *(const float4*)&As[buf][kk][(ty<<3)+4];
            ulonglong2 q0 = *(const ulonglong2*)&Ws[buf][kk][tx<<3];
            ulonglong2 q1 = *(const ulonglong2*)&Ws[buf][kk][(tx<<3)+4];
            unsigned long long a2[8];
            asm("mov.b64 %0,{%1,%1};" : "=l"(a2[0]) : "f"(af0.x));
            asm("mov.b64 %0,{%1,%1};" : "=l"(a2[1]) : "f"(af0.y));
            asm("mov.b64 %0,{%1,%1};" : "=l"(a2[2]) : "f"(af0.z));
            asm("mov.b64 %0,{%1,%1};" : "=l"(a2[3]) : "f"(af0.w));
            asm("mov.b64 %0,{%1,%1};" : "=l"(a2[4]) : "f"(af1.x));
            asm("mov.b64 %0,{%1,%1};" : "=l"(a2[5]) : "f"(af1.y));
            asm("mov.b64 %0,{%1,%1};" : "=l"(a2[6]) : "f"(af1.z));
            asm("mov.b64 %0,{%1,%1};" : "=l"(a2[7]) : "f"(af1.w));
            #pragma unroll
            for (int i=0;i<8;i++) {
                FMA2(acc2[i][0], a2[i], q0.x);
                FMA2(acc2[i][1], a2[i], q0.y);
                FMA2(acc2[i][2], a2[i], q1.x);
                FMA2(acc2[i][3], a2[i], q1.y);
            }
        }
        if (it < NIT) {
            int nb = buf ^ 1;
            As[nb][(ac<<2)+0][ar]=av.x; As[nb][(ac<<2)+1][ar]=av.y;
            As[nb][(ac<<2)+2][ar]=av.z; As[nb][(ac<<2)+3][ar]=av.w;
            *(float4*)&Ws[nb][wr][wc<<2] = wv;
            __syncthreads();
            buf = nb;
        }
    }
    #pragma unroll
    for (int i=0;i<8;i++) {
        float2 p0 = *reinterpret_cast<float2*>(&acc2[i][0]);
        float2 p1 = *reinterpret_cast<float2*>(&acc2[i][1]);
        float2 p2 = *reinterpret_cast<float2*>(&acc2[i][2]);
        float2 p3 = *reinterpret_cast<float2*>(&acc2[i][3]);
        float4 v0 = make_float4(p0.x, p0.y, p1.x, p1.y);
        float4 v1 = make_float4(p2.x, p2.y, p3.x, p3.y);
        float* crow = C + (size_t)(m0 + (ty<<3) + i)*ldc + n0 + (tx<<3);
        if (bias) {
            const float* bp = bias + n0 + (tx<<3);
            float4 b0=*(const float4*)bp, b1=*(const float4*)(bp+4);
            v0.x+=b0.x; v0.y+=b0.y; v0.z+=b0.z; v0.w+=b0.w;
            v1.x+=b1.x; v1.y+=b1.y; v1.z+=b1.z; v1.w+=b1.w;
        }
        if (accflag) {
            float4 c0=*(const float4*)crow, c1=*(const float4*)(crow+4);
            v0.x+=c0.x; v0.y+=c0.y; v0.z+=c0.z; v0.w+=c0.w;
            v1.x+=c1.x; v1.y+=c1.y; v1.z+=c1.z; v1.w+=c1.w;
        }
        *(float4*)crow = v0; *(float4*)(crow+4) = v1;
    }
}

// ---------------- cluster LSTM recurrence (shared by enc/dec via mode) ----------------
// One cluster of 8 CTAs handles 4 batches. Rank r owns hidden units j in [32r,32r+32)
// for all 4 gates (cols {256g + 32r + jj}). h state double-buffered in smem; new h
// broadcast to peers via st.shared::cluster; one cluster barrier per step.
// Thread layout (128 threads): warp w = gate, lane l: b = l>>3, cs = l&7;
// thread computes 4 cols: cidx = 32w + cs + 8q.
__device__ __forceinline__ void lstm_cluster_body(
    const float* __restrict__ Whh,       // [256][1024]
    const float* __restrict__ Zpre,      // [b*SS+s][1024] or null (dec)
    const float* __restrict__ Dpre,      // dec: [b*SS+t-1][1024], or null
    const float* __restrict__ bias,      // dec: [1024], or null
    const float* __restrict__ cinit,     // dec: g_hn (c0 = hn[b][S-1]), or null
    float* __restrict__ hout,            // [b*SS+s][256]
    int rank, int bg, int dir)
{
    extern __shared__ float sm[];
    const int tid = threadIdx.x;
    const int w = tid >> 5, l = tid & 31;
    const int b = l >> 3, cs = l & 7;

    // load W slice transposed: Wsh[cidx][k] = Whh[k][col(cidx)], cidx = tid
    {
        const int lcol = 256*(tid>>5) + 32*rank + (tid&31);
        float* wdst = &sm[W_OFF + tid*260];
        #pragma unroll 8
        for (int k = 0; k < 256; ++k)
            wdst[k] = Whh[(size_t)k*GG + lcol];
    }
    // zero h buffer 0
    for (int i = tid; i < 4*260; i += 128) sm[H_OFF + i] = 0.0f;
    __syncthreads();
    asm volatile("barrier.cluster.arrive.aligned;" ::: "memory");
    asm volatile("barrier.cluster.wait.aligned;" ::: "memory");

    const float* wp0 = &sm[W_OFF + (32*w + cs +  0)*260];
    const float* wp1 = &sm[W_OFF + (32*w + cs +  8)*260];
    const float* wp2 = &sm[W_OFF + (32*w + cs + 16)*260];
    const float* wp3 = &sm[W_OFF + (32*w + cs + 24)*260];
    const int c0g = 256*w + 32*rank + cs;   // global col of q=0
    const size_t brow = (size_t)(4*bg + b); // batch of this dot thread
    float* zslot = &sm[Z_OFF + (b*4 + w)*32 + cs];

    float bz0=0.f, bz1=0.f, bz2=0.f, bz3=0.f;
    if (bias) { bz0=bias[c0g]; bz1=bias[c0g+8]; bz2=bias[c0g+16]; bz3=bias[c0g+24]; }

    // cell role: cb = tid>>5 (batch), jj = tid&31 (hidden unit within rank's slice)
    const int cb = w, jj = l;
    const int jglob = 32*rank + jj;
    float cst = 0.0f;
    if (cinit) cst = cinit[((size_t)(4*bg+cb)*SS + (SS-1))*HH + jglob];
    float* zc = &sm[Z_OFF + cb*128 + jj];
    const size_t hrowbase = (size_t)(4*bg+cb)*SS;

    int buf = 0;
    for (int t = 0; t < SS; ++t) {
        const int tt = dir ? (SS-1-t) : t;
        float zp0, zp1, zp2, zp3;
        if (Zpre) {
            const float* zr = Zpre + (brow*SS + tt)*GG;
            zp0 = __ldcg(zr + c0g);      zp1 = __ldcg(zr + c0g + 8);
            zp2 = __ldcg(zr + c0g + 16); zp3 = __ldcg(zr + c0g + 24);
        } else {
            zp0 = bz0; zp1 = bz1; zp2 = bz2; zp3 = bz3;
            if (t > 0) {
                const float* zr = Dpre + (brow*SS + (t-1))*GG;
                zp0 += __ldcg(zr + c0g);      zp1 += __ldcg(zr + c0g + 8);
                zp2 += __ldcg(zr + c0g + 16); zp3 += __ldcg(zr + c0g + 24);
            }
        }
        const float* hr = &sm[H_OFF + (buf*4 + b)*260];
        unsigned long long a0x=0,a0y=0,a1x=0,a1y=0,a2x=0,a2y=0,a3x=0,a3y=0;
        #pragma unroll 8
        for (int k = 0; k < 256; k += 4) {
            ulonglong2 hp = *(const ulonglong2*)(hr + k);
            ulonglong2 q0 = *(const ulonglong2*)(wp0 + k);
            ulonglong2 q1 = *(const ulonglong2*)(wp1 + k);
            ulonglong2 q2 = *(const ulonglong2*)(wp2 + k);
            ulonglong2 q3 = *(const ulonglong2*)(wp3 + k);
            FMA2(a0x,hp.x,q0.x); FMA2(a0y,hp.y,q0.y);
            FMA2(a1x,hp.x,q1.x); FMA2(a1y,hp.y,q1.y);
            FMA2(a2x,hp.x,q2.x); FMA2(a2y,hp.y,q2.y);
            FMA2(a3x,hp.x,q3.x); FMA2(a3y,hp.y,q3.y);
        }
        zslot[0]  = zp0 + hadd2(a0x) + hadd2(a0y);
        zslot[8]  = zp1 + hadd2(a1x) + hadd2(a1y);
        zslot[16] = zp2 + hadd2(a2x) + hadd2(a2y);
        zslot[24] = zp3 + hadd2(a3x) + hadd2(a3y);
        __syncthreads();

        // cell (all 128 threads)
        const int nbuf = buf ^ 1;
        {
            float zi = zc[0], zf = zc[32], zg = zc[64], zo = zc[96];
            cst = sigf(zf)*cst + sigf(zi)*tanhf(zg);
            float hh = sigf(zo)*tanhf(cst);
            float* lp = &sm[H_OFF + (nbuf*4 + cb)*260 + jglob];
            unsigned la = (unsigned)__cvta_generic_to_shared(lp);
            #pragma unroll
            for (int r = 0; r < CL; ++r) {
                unsigned ra;
                asm("mapa.shared::cluster.u32 %0, %1, %2;" : "=r"(ra) : "r"(la), "r"(r));
                asm volatile("st.shared::cluster.f32 [%0], %1;" :: "r"(ra), "f"(hh));
            }
            hout[(hrowbase + tt)*HH + jglob] = hh;
        }
        asm volatile("barrier.cluster.arrive.aligned;" ::: "memory");
        buf = nbuf;
        asm volatile("barrier.cluster.wait.aligned;" ::: "memory");
    }
}

// encoder: grid 64 = 2 dir x 4 bg x 8 rank
__global__ void __cluster_dims__(CL,1,1) __launch_bounds__(128,1)
enc_rnn_cl(const float* __restrict__ Whh_f, const float* __restrict__ Whh_b)
{
    const int bx = blockIdx.x;
    const int rank = bx & 7;
    const int cid  = bx >> 3;
    const int dir  = cid >> 2;
    const int bg   = cid & 3;
    const float* Whh = dir ? Whh_b : Whh_f;
    const float* Z   = dir ? g_Zb  : g_Zf;
    float* hout      = dir ? g_hb  : g_hn;
    lstm_cluster_body(Whh, Z, nullptr, nullptr, nullptr, hout, rank, bg, dir);
}

// decoder: grid 32 = 4 bg x 8 rank
__global__ void __cluster_dims__(CL,1,1) __launch_bounds__(128,1)
dec_rnn_cl(const float* __restrict__ Whh, const float* __restrict__ bias)
{
    const int bx = blockIdx.x;
    const int rank = bx & 7;
    const int bg   = bx >> 3;
    lstm_cluster_body(Whh, nullptr, g_D, bias, g_hn, g_Hd, rank, bg, 0);
}

// ---------------- bond chain: one block per batch; lazy masked argmax ----------------
__global__ __launch_bounds__(256) void chain_kernel(const float* __restrict__ vt1,
                                                    float* __restrict__ out)
{
    const int b = blockIdx.x, tid = threadIdx.x;
    __shared__ float v[WT], u[WT];
    __shared__ float smax[256];
    __shared__ int   sidx[256];
    for (int i = tid; i < WT; i += 256) v[i] = vt1[i];
    for (int s = tid; s < SS; s += 256) out[s*BB + b] = 0.0f;
    __syncthreads();
    int bond = 0;
    for (int iter = 0; iter < SS; ++iter) {
        const int t = bond;
        for (int i = tid; i < WT; i += 256) u[i] = g_U[(((size_t)b<<10) + t)*WT + i];
        __syncthreads();
        float best = -INFINITY; int bidx = SS;
        for (int j = t + tid; j < SS; j += 256) {
            const float* crow = &g_C[(((size_t)b<<10) + j)*WT];
            float acc = 0.0f;
            #pragma unroll 8
            for (int k = 0; k < WT; k += 4) {
                float4 cv = *(const float4*)&crow[k];
                float4 uv = *(const float4*)&u[k];
                float4 vv = *(const float4*)&v[k];
                acc += tanhf(cv.x+uv.x)*vv.x;
                acc += tanhf(cv.y+uv.y)*vv.y;
                acc += tanhf(cv.z+uv.z)*vv.z;
                acc += tanhf(cv.w+uv.w)*vv.w;
            }
            if (acc > best) { best = acc; bidx = j; }
        }
        smax[tid] = best; sidx[tid] = bidx;
        __syncthreads();
        for (int off = 128; off; off >>= 1) {
            if (tid < off) {
                float ov = smax[tid+off]; int oi = sidx[tid+off];
                if (ov > smax[tid] || (ov == smax[tid] && oi < sidx[tid])) { smax[tid]=ov; sidx[tid]=oi; }
            }
            __syncthreads();
        }
        const int r = sidx[0];
        if (tid == 0) out[r*BB + b] = 1.0f;
        __syncthreads();
        if (r == t) break;
        bond = r;
    }
}

extern "C" void kernel_launch(void* const* d_in, const int* in_sizes, int n_in,
                              void* d_out, int out_size)
{
    const float* x    = (const float*)d_in[0];
    const float* eWf  = (const float*)d_in[1];
    const float* eUf  = (const float*)d_in[2];
    const float* ebf  = (const float*)d_in[3];
    const float* eWb  = (const float*)d_in[4];
    const float* eUb  = (const float*)d_in[5];
    const float* ebb  = (const float*)d_in[6];
    const float* dW   = (const float*)d_in[7];   // [512,1024]
    const float* dU   = (const float*)d_in[8];
    const float* db   = (const float*)d_in[9];
    const float* W1   = (const float*)d_in[10];  // [512,256]
    const float* W2   = (const float*)d_in[11];
    const float* W3   = (const float*)d_in[12];
    const float* W4   = (const float*)d_in[13];
    const float* vt1  = (const float*)d_in[14];
    float* out = (float*)d_out;

    float *Zf, *Zb, *D, *hn, *hb, *Hd, *C, *U;
    cudaGetSymbolAddress((void**)&Zf, g_Zf);
    cudaGetSymbolAddress((void**)&Zb, g_Zb);
    cudaGetSymbolAddress((void**)&D,  g_D);
    cudaGetSymbolAddress((void**)&hn, g_hn);
    cudaGetSymbolAddress((void**)&hb, g_hb);
    cudaGetSymbolAddress((void**)&Hd, g_Hd);
    cudaGetSymbolAddress((void**)&C,  g_C);
    cudaGetSymbolAddress((void**)&U,  g_U);

    cudaFuncSetAttribute(enc_rnn_cl, cudaFuncAttributeMaxDynamicSharedMemorySize, SMEM_BYTES);
    cudaFuncSetAttribute(dec_rnn_cl, cudaFuncAttributeMaxDynamicSharedMemorySize, SMEM_BYTES);

    dim3 gW(GG/128, MM/128);   // N=1024
    dim3 gN(WT/128, MM/128);   // N=256
    sgemm_db<<<gW,256>>>(x, EE, eWf, GG, Zf, GG, EE, ebf, 0);
    sgemm_db<<<gW,256>>>(x, EE, eWb, GG, Zb, GG, EE, ebb, 0);
    sgemm_db<<<gW,256>>>(x, EE, dW,              GG, D, GG, EE, nullptr, 0);
    enc_rnn_cl<<<64, 128, SMEM_BYTES>>>(eUf, eUb);
    sgemm_db<<<gW,256>>>(hn, HH, dW + 256*GG,    GG, D, GG, HH, nullptr, 1);
    sgemm_db<<<gN,256>>>(hn, HH, W1,            WT, C, WT, HH, nullptr, 0);
    sgemm_db<<<gN,256>>>(hb, HH, W1 + 256*WT,   WT, C, WT, HH, nullptr, 1);
    sgemm_db<<<gN,256>>>(x,  EE, W2,            WT, C, WT, EE, nullptr, 1);
    sgemm_db<<<gN,256>>>(x,  EE, W3,            WT, U, WT, EE, nullptr, 0);
    dec_rnn_cl<<<32, 128, SMEM_BYTES>>>(dU, db);
    sgemm_db<<<gN,256>>>(Hd, HH, W4,            WT, U, WT, HH, nullptr, 1);
    chain_kernel<<<BB,256>>>(vt1, out);
}

// round 14
// speedup vs baseline: 1.3671x; 1.0786x over previous
#include <cuda_runtime.h>
#include <math.h>

#define BB 16
#define SS 1024
#define EE 256
#define HH 256
#define GG 1024
#define WT 256
#define MM (BB*SS)
#define CL 8

// ---------------- scratch (__device__ globals; no alloc allowed) ----------------
__device__ float g_Zf[(size_t)MM*GG];
__device__ float g_Zb[(size_t)MM*GG];
__device__ float g_D [(size_t)MM*GG];
__device__ float g_hn[(size_t)MM*HH];
__device__ float g_hb[(size_t)MM*HH];
__device__ float g_Hd[(size_t)MM*HH];
__device__ float g_C [(size_t)MM*WT];
__device__ float g_U [(size_t)MM*WT];

__device__ __forceinline__ float sigf(float x){ return 1.0f/(1.0f+expf(-x)); }
__device__ __forceinline__ float hadd2(unsigned long long v){
    float2 f = *reinterpret_cast<float2*>(&v); return f.x + f.y;
}
#define FMA2(acc,a,b) asm("fma.rn.f32x2 %0,%1,%2,%0;" : "+l"(acc) : "l"(a), "l"(b))

// ---------------- fp32 SGEMM, double-buffered, packed f32x2 FMA ----------------
__global__ __launch_bounds__(256, 2) void sgemm_db(
    const float* __restrict__ A, int lda,
    const float* __restrict__ W, int ldw,
    float* __restrict__ C, int ldc,
    int K, const float* __restrict__ bias, int accflag)
{
    __shared__ float As[2][8][132];
    __shared__ float Ws[2][8][132];
    const int tid = threadIdx.x;
    const int m0 = blockIdx.y << 7, n0 = blockIdx.x << 7;
    const int ar = tid >> 1, ac = tid & 1;
    const int wr = tid >> 5, wc = tid & 31;
    const int ty = tid >> 4, tx = tid & 15;

    unsigned long long acc2[8][4];
    #pragma unroll
    for (int i=0;i<8;i++){
        #pragma unroll
        for (int j=0;j<4;j++) acc2[i][j] = 0ull;
    }
    const float* Ap = A + (size_t)(m0+ar)*lda + (ac<<2);
    const float* Wp = W + (size_t)wr*ldw + n0 + (wc<<2);
    {
        float4 av = *(const float4*)(Ap);
        float4 wv = *(const float4*)(Wp);
        As[0][(ac<<2)+0][ar]=av.x; As[0][(ac<<2)+1][ar]=av.y;
        As[0][(ac<<2)+2][ar]=av.z; As[0][(ac<<2)+3][ar]=av.w;
        *(float4*)&Ws[0][wr][wc<<2] = wv;
    }
    __syncthreads();
    const int NIT = K >> 3;
    int buf = 0;
    for (int it = 1; it <= NIT; ++it) {
        float4 av, wv;
        if (it < NIT) {
            av = *(const float4*)(Ap + (it<<3));
            wv = *(const float4*)(Wp + (size_t)(it<<3)*ldw);
        }
        #pragma unroll
        for (int kk=0;kk<8;kk++) {
            float4 af0 = *(const float4*)&As[buf][kk][ty<<3];
            float4 af1 = *(const float4*)&As[buf][kk][(ty<<3)+4];
            ulonglong2 q0 = *(const ulonglong2*)&Ws[buf][kk][tx<<3];
            ulonglong2 q1 = *(const ulonglong2*)&Ws[buf][kk][(tx<<3)+4];
            unsigned long long a2[8];
            asm("mov.b64 %0,{%1,%1};" : "=l"(a2[0]) : "f"(af0.x));
            asm("mov.b64 %0,{%1,%1};" : "=l"(a2[1]) : "f"(af0.y));
            asm("mov.b64 %0,{%1,%1};" : "=l"(a2[2]) : "f"(af0.z));
            asm("mov.b64 %0,{%1,%1};" : "=l"(a2[3]) : "f"(af0.w));
            asm("mov.b64 %0,{%1,%1};" : "=l"(a2[4]) : "f"(af1.x));
            asm("mov.b64 %0,{%1,%1};" : "=l"(a2[5]) : "f"(af1.y));
            asm("mov.b64 %0,{%1,%1};" : "=l"(a2[6]) : "f"(af1.z));
            asm("mov.b64 %0,{%1,%1};" : "=l"(a2[7]) : "f"(af1.w));
            #pragma unroll
            for (int i=0;i<8;i++) {
                FMA2(acc2[i][0], a2[i], q0.x);
                FMA2(acc2[i][1], a2[i], q0.y);
                FMA2(acc2[i][2], a2[i], q1.x);
                FMA2(acc2[i][3], a2[i], q1.y);
            }
        }
        if (it < NIT) {
            int nb = buf ^ 1;
            As[nb][(ac<<2)+0][ar]=av.x; As[nb][(ac<<2)+1][ar]=av.y;
            As[nb][(ac<<2)+2][ar]=av.z; As[nb][(ac<<2)+3][ar]=av.w;
            *(float4*)&Ws[nb][wr][wc<<2] = wv;
            __syncthreads();
            buf = nb;
        }
    }
    #pragma unroll
    for (int i=0;i<8;i++) {
        float2 p0 = *reinterpret_cast<float2*>(&acc2[i][0]);
        float2 p1 = *reinterpret_cast<float2*>(&acc2[i][1]);
        float2 p2 = *reinterpret_cast<float2*>(&acc2[i][2]);
        float2 p3 = *reinterpret_cast<float2*>(&acc2[i][3]);
        float4 v0 = make_float4(p0.x, p0.y, p1.x, p1.y);
        float4 v1 = make_float4(p2.x, p2.y, p3.x, p3.y);
        float* crow = C + (size_t)(m0 + (ty<<3) + i)*ldc + n0 + (tx<<3);
        if (bias) {
            const float* bp = bias + n0 + (tx<<3);
            float4 b0=*(const float4*)bp, b1=*(const float4*)(bp+4);
            v0.x+=b0.x; v0.y+=b0.y; v0.z+=b0.z; v0.w+=b0.w;
            v1.x+=b1.x; v1.y+=b1.y; v1.z+=b1.z; v1.w+=b1.w;
        }
        if (accflag) {
            float4 c0=*(const float4*)crow, c1=*(const float4*)(crow+4);
            v0.x+=c0.x; v0.y+=c0.y; v0.z+=c0.z; v0.w+=c0.w;
            v1.x+=c1.x; v1.y+=c1.y; v1.z+=c1.z; v1.w+=c1.w;
        }
        *(float4*)crow = v0; *(float4*)(crow+4) = v1;
    }
}

// ---------------- persistent-register cluster LSTM ----------------
// Cluster of 8 CTAs handles 2 batches. Rank r owns hidden units [32r,32r+32) for
// all 4 gates (128 local cols). 256 threads: thread t -> col c=t>>1, k-half kh=t&1;
// 128 W floats live in 64 packed f32x2 registers. h state double-buffered in smem,
// broadcast via st.shared::cluster; one split cluster barrier per step.
__device__ __forceinline__ void lstm_persist_body(
    const float* __restrict__ Whh,       // [256][1024]
    const float* __restrict__ Zpre,      // enc: [b*SS+s][1024], or null
    const float* __restrict__ Dpre,      // dec: [b*SS+t-1][1024], or null
    const float* __restrict__ bias,      // dec: [1024], or null
    const float* __restrict__ cinit,     // dec: g_hn (c0 = hn[b][S-1]), or null
    float* __restrict__ hout,            // [b*SS+s][256]
    int rank, int bg, int dir)
{
    __shared__ float hsh[2][2][264];
    __shared__ float zsh[2][132];
    const int tid = threadIdx.x;
    const int c = tid >> 1, kh = tid & 1;
    const int gcol = ((c>>5)<<8) + 32*rank + (c&31);

    // --- load register-resident W slice ---
    unsigned long long Wreg[64];
    {
        const float* wp = Whh + (size_t)(128*kh)*GG + gcol;
        #pragma unroll
        for (int i = 0; i < 64; ++i) {
            float w0 = wp[(size_t)(2*i)*GG];
            float w1 = wp[(size_t)(2*i+1)*GG];
            asm("mov.b64 %0,{%1,%2};" : "=l"(Wreg[i]) : "f"(w0), "f"(w1));
        }
    }
    float bz = bias ? bias[gcol] : 0.0f;

    // zero h buffers
    for (int i = tid; i < 2*2*264; i += 256) (&hsh[0][0][0])[i] = 0.0f;

    // cell-role state (threads 0..63): b = u>>5, jj = u&31
    const int cb = tid >> 5, cjj = tid & 31;
    const int jglob = 32*rank + cjj;
    float cst = 0.0f;
    if (cinit && tid < 64)
        cst = cinit[((size_t)(2*bg + cb)*SS + (SS-1))*HH + jglob];

    __syncthreads();
    asm volatile("barrier.cluster.arrive.aligned;" ::: "memory");
    asm volatile("barrier.cluster.wait.aligned;" ::: "memory");

    const int bw = kh;                        // batch this thread writes z for
    const size_t zrow_base = (size_t)(2*bg + bw)*SS;

    int buf = 0;
    for (int t = 0; t < SS; ++t) {
        const int tt = dir ? (SS-1-t) : t;
        // prefetch z pre-activation for (bw, this col)
        float zp;
        if (Zpre) {
            zp = __ldcg(Zpre + (zrow_base + tt)*GG + gcol);
        } else {
            zp = bz;
            if (t > 0) zp += __ldcg(Dpre + (zrow_base + (t-1))*GG + gcol);
        }
        // dot: both batches, register W, broadcast h
        const ulonglong2* h0 = (const ulonglong2*)&hsh[buf][0][kh*128];
        const ulonglong2* h1 = (const ulonglong2*)&hsh[buf][1][kh*128];
        unsigned long long a00=0,a01=0,a10=0,a11=0;
        #pragma unroll
        for (int i = 0; i < 32; ++i) {
            ulonglong2 p0 = h0[i];
            ulonglong2 p1 = h1[i];
            FMA2(a00, p0.x, Wreg[2*i]); FMA2(a01, p0.y, Wreg[2*i+1]);
            FMA2(a10, p1.x, Wreg[2*i]); FMA2(a11, p1.y, Wreg[2*i+1]);
        }
        float d0 = hadd2(a00) + hadd2(a01);
        float d1 = hadd2(a10) + hadd2(a11);
        d0 += __shfl_xor_sync(0xffffffffu, d0, 1);
        d1 += __shfl_xor_sync(0xffffffffu, d1, 1);
        zsh[bw][c] = zp + (kh ? d1 : d0);
        __syncthreads();

        const int nbuf = buf ^ 1;
        if (tid < 64) {
            float zi = zsh[cb][cjj], zf = zsh[cb][32+cjj];
            float zg = zsh[cb][64+cjj], zo = zsh[cb][96+cjj];
            cst = sigf(zf)*cst + sigf(zi)*tanhf(zg);
            float hh = sigf(zo)*tanhf(cst);
            float* lp = &hsh[nbuf][cb][jglob];
            unsigned la = (unsigned)__cvta_generic_to_shared(lp);
            #pragma unroll
            for (int r = 0; r < CL; ++r) {
                unsigned ra;
                asm("mapa.shared::cluster.u32 %0, %1, %2;" : "=r"(ra) : "r"(la), "r"(r));
                asm volatile("st.shared::cluster.f32 [%0], %1;" :: "r"(ra), "f"(hh));
            }
            hout[((size_t)(2*bg + cb)*SS + tt)*HH + jglob] = hh;
        }
        asm volatile("barrier.cluster.arrive.aligned;" ::: "memory");
        buf = nbuf;
        asm volatile("barrier.cluster.wait.aligned;" ::: "memory");
    }
}

// encoder: 16 clusters (2 dir x 8 bg) x 8 ranks = 128 blocks
__global__ void __cluster_dims__(CL,1,1) __launch_bounds__(256,1)
enc_rnn_cl(const float* __restrict__ Whh_f, const float* __restrict__ Whh_b)
{
    const int bx = blockIdx.x;
    const int rank = bx & 7;
    const int cid  = bx >> 3;
    const int dir  = cid >> 3;
    const int bg   = cid & 7;
    const float* Whh = dir ? Whh_b : Whh_f;
    const float* Z   = dir ? g_Zb  : g_Zf;
    float* hout      = dir ? g_hb  : g_hn;
    lstm_persist_body(Whh, Z, nullptr, nullptr, nullptr, hout, rank, bg, dir);
}

// decoder: 8 clusters (8 bg) x 8 ranks = 64 blocks
__global__ void __cluster_dims__(CL,1,1) __launch_bounds__(256,1)
dec_rnn_cl(const float* __restrict__ Whh, const float* __restrict__ bias)
{
    const int bx = blockIdx.x;
    const int rank = bx & 7;
    const int bg   = bx >> 3;
    lstm_persist_body(Whh, nullptr, g_D, bias, g_hn, g_Hd, rank, bg, 0);
}

// ---------------- bond chain: one block per batch; lazy masked argmax ----------------
__global__ __launch_bounds__(256) void chain_kernel(const float* __restrict__ vt1,
                                                    float* __restrict__ out)
{
    const int b = blockIdx.x, tid = threadIdx.x;
    __shared__ float v[WT], u[WT];
    __shared__ float smax[256];
    __shared__ int   sidx[256];
    for (int i = tid; i < WT; i += 256) v[i] = vt1[i];
    for (int s = tid; s < SS; s += 256) out[s*BB + b] = 0.0f;
    __syncthreads();
    int bond = 0;
    for (int iter = 0; iter < SS; ++iter) {
        const int t = bond;
        for (int i = tid; i < WT; i += 256) u[i] = g_U[(((size_t)b<<10) + t)*WT + i];
        __syncthreads();
        float best = -INFINITY; int bidx = SS;
        for (int j = t + tid; j < SS; j += 256) {
            const float* crow = &g_C[(((size_t)b<<10) + j)*WT];
            float acc = 0.0f;
            #pragma unroll 8
            for (int k = 0; k < WT; k += 4) {
                float4 cv = *(const float4*)&crow[k];
                float4 uv = *(const float4*)&u[k];
                float4 vv = *(const float4*)&v[k];
                acc += tanhf(cv.x+uv.x)*vv.x;
                acc += tanhf(cv.y+uv.y)*vv.y;
                acc += tanhf(cv.z+uv.z)*vv.z;
                acc += tanhf(cv.w+uv.w)*vv.w;
            }
            if (acc > best) { best = acc; bidx = j; }
        }
        smax[tid] = best; sidx[tid] = bidx;
        __syncthreads();
        for (int off = 128; off; off >>= 1) {
            if (tid < off) {
                float ov = smax[tid+off]; int oi = sidx[tid+off];
                if (ov > smax[tid] || (ov == smax[tid] && oi < sidx[tid])) { smax[tid]=ov; sidx[tid]=oi; }
            }
            __syncthreads();
        }
        const int r = sidx[0];
        if (tid == 0) out[r*BB + b] = 1.0f;
        __syncthreads();
        if (r == t) break;
        bond = r;
    }
}

extern "C" void kernel_launch(void* const* d_in, const int* in_sizes, int n_in,
                              void* d_out, int out_size)
{
    const float* x    = (const float*)d_in[0];
    const float* eWf  = (const float*)d_in[1];
    const float* eUf  = (const float*)d_in[2];
    const float* ebf  = (const float*)d_in[3];
    const float* eWb  = (const float*)d_in[4];
    const float* eUb  = (const float*)d_in[5];
    const float* ebb  = (const float*)d_in[6];
    const float* dW   = (const float*)d_in[7];   // [512,1024]
    const float* dU   = (const float*)d_in[8];
    const float* db   = (const float*)d_in[9];
    const float* W1   = (const float*)d_in[10];  // [512,256]
    const float* W2   = (const float*)d_in[11];
    const float* W3   = (const float*)d_in[12];
    const float* W4   = (const float*)d_in[13];
    const float* vt1  = (const float*)d_in[14];
    float* out = (float*)d_out;

    float *Zf, *Zb, *D, *hn, *hb, *Hd, *C, *U;
    cudaGetSymbolAddress((void**)&Zf, g_Zf);
    cudaGetSymbolAddress((void**)&Zb, g_Zb);
    cudaGetSymbolAddress((void**)&D,  g_D);
    cudaGetSymbolAddress((void**)&hn, g_hn);
    cudaGetSymbolAddress((void**)&hb, g_hb);
    cudaGetSymbolAddress((void**)&Hd, g_Hd);
    cudaGetSymbolAddress((void**)&C,  g_C);
    cudaGetSymbolAddress((void**)&U,  g_U);

    dim3 gW(GG/128, MM/128);   // N=1024
    dim3 gN(WT/128, MM/128);   // N=256
    sgemm_db<<<gW,256>>>(x, EE, eWf, GG, Zf, GG, EE, ebf, 0);
    sgemm_db<<<gW,256>>>(x, EE, eWb, GG, Zb, GG, EE, ebb, 0);
    sgemm_db<<<gW,256>>>(x, EE, dW,              GG, D, GG, EE, nullptr, 0);
    enc_rnn_cl<<<128, 256>>>(eUf, eUb);
    sgemm_db<<<gW,256>>>(hn, HH, dW + 256*GG,    GG, D, GG, HH, nullptr, 1);
    sgemm_db<<<gN,256>>>(hn, HH, W1,            WT, C, WT, HH, nullptr, 0);
    sgemm_db<<<gN,256>>>(hb, HH, W1 + 256*WT,   WT, C, WT, HH, nullptr, 1);
    sgemm_db<<<gN,256>>>(x,  EE, W2,            WT, C, WT, EE, nullptr, 1);
    sgemm_db<<<gN,256>>>(x,  EE, W3,            WT, U, WT, EE, nullptr, 0);
    dec_rnn_cl<<<64, 256>>>(dU, db);
    sgemm_db<<<gN,256>>>(Hd, HH, W4,            WT, U, WT, HH, nullptr, 1);
    chain_kernel<<<BB,256>>>(vt1, out);
}